// round 6
// baseline (speedup 1.0000x reference)
#include <cuda_runtime.h>

// Problem constants
#define BB 8
#define NN 1024
#define FF 2048
#define CC 4
#define NTOK (BB * NN)            // 8192 tokens
#define VEC_ELEMS (BB * NN * FF)  // 16777216 floats
#define BCN (BB * CC)             // 32 (b,c) pairs

// Scratch (static device globals — no allocation allowed)
__device__ float g_Wpart[16][8][2048];  // [h-chunk][row r][f], r = c + 4*half
__device__ float g_W[8 * 2048];         // Weff rows: r<4 -> Wa[c], r>=4 -> Wb[c]
__device__ float g_cst[4];              // W2 @ b1 + b2
__device__ float g_EA[BCN * NN];        // exp(p1[b,n,c] + const[c]),  [(b*4+c)*1024 + n]
__device__ float g_EB[BCN * NN];        // exp(p2[b,n,c])

// ---------------------------------------------------------------------------
// Kernel 1: partial Weff[r][f] = sum_{h in chunk} W2[c][h] * W1[h][f']
// ---------------------------------------------------------------------------
__global__ void k1_weff_part(const float* __restrict__ W1,
                             const float* __restrict__ W2) {
    __shared__ float sW2[4 * 64];
    const int tid = threadIdx.x;
    const int h0 = blockIdx.y * 64;
    if (tid < 256) sW2[tid] = W2[(tid >> 6) * 1024 + h0 + (tid & 63)];
    __syncthreads();

    const int fp = blockIdx.x * 256 + tid;  // 0..4095 (column of W1)
    float a0 = 0.f, a1 = 0.f, a2 = 0.f, a3 = 0.f;
    const float* w1p = W1 + (size_t)h0 * 4096 + fp;
#pragma unroll 16
    for (int hh = 0; hh < 64; hh++) {
        float w1 = w1p[(size_t)hh * 4096];
        a0 = fmaf(sW2[hh], w1, a0);
        a1 = fmaf(sW2[64 + hh], w1, a1);
        a2 = fmaf(sW2[128 + hh], w1, a2);
        a3 = fmaf(sW2[192 + hh], w1, a3);
    }
    const int half = fp >> 11;
    const int f = fp & 2047;
    const int rb = half * 4;
    g_Wpart[blockIdx.y][rb + 0][f] = a0;
    g_Wpart[blockIdx.y][rb + 1][f] = a1;
    g_Wpart[blockIdx.y][rb + 2][f] = a2;
    g_Wpart[blockIdx.y][rb + 3][f] = a3;
}

// ---------------------------------------------------------------------------
// Kernel 1b: reduce partials into g_W; one warp also computes g_cst
// ---------------------------------------------------------------------------
__global__ void k1b_reduce(const float* __restrict__ W2,
                           const float* __restrict__ b1,
                           const float* __restrict__ b2) {
    const int idx = blockIdx.x * 256 + threadIdx.x;  // 0..16383
    const int r = idx >> 11, f = idx & 2047;
    float s = 0.f;
#pragma unroll
    for (int p = 0; p < 16; p++) s += g_Wpart[p][r][f];
    g_W[r * 2048 + f] = s;

    if (blockIdx.x == 0 && threadIdx.x < 32) {
        const int lane = threadIdx.x;
        float c0 = 0.f, c1 = 0.f, c2 = 0.f, c3 = 0.f;
        for (int h = lane; h < 1024; h += 32) {
            float bv = b1[h];
            c0 = fmaf(W2[h], bv, c0);
            c1 = fmaf(W2[1024 + h], bv, c1);
            c2 = fmaf(W2[2048 + h], bv, c2);
            c3 = fmaf(W2[3072 + h], bv, c3);
        }
#pragma unroll
        for (int off = 16; off; off >>= 1) {
            c0 += __shfl_xor_sync(~0u, c0, off);
            c1 += __shfl_xor_sync(~0u, c1, off);
            c2 += __shfl_xor_sync(~0u, c2, off);
            c3 += __shfl_xor_sync(~0u, c3, off);
        }
        if (lane == 0) {
            g_cst[0] = c0 + b2[0];
            g_cst[1] = c1 + b2[1];
            g_cst[2] = c2 + b2[2];
            g_cst[3] = c3 + b2[3];
        }
    }
}

// ---------------------------------------------------------------------------
// Kernel 2 (chunked): projections + fused vectors copy for 2048 tokens.
// Weights staged in 64 KB smem. One warp per 2 tokens; 16 tokens/block;
// 128 blocks per chunk. blockOffset selects the chunk.
// ---------------------------------------------------------------------------
__global__ void __launch_bounds__(256) k2_proj(const float4* __restrict__ vec4,
                                               float4* __restrict__ outv4,
                                               int blockOffset) {
    extern __shared__ float4 sW[];  // 4096 float4 = 64 KB = all of g_W
    const float4* gW4 = reinterpret_cast<const float4*>(g_W);
    for (int s = threadIdx.x; s < 4096; s += 256) sW[s] = gW4[s];
    __syncthreads();

    const int lane = threadIdx.x & 31;
    const int wid = threadIdx.x >> 5;
    const int t0 = ((blockOffset + blockIdx.x) * 8 + wid) * 2;

    const float4* vp = vec4 + (size_t)t0 * 512;
    float4* op = outv4 + (size_t)t0 * 512;

    float acc[8][2];
#pragma unroll
    for (int r = 0; r < 8; r++) {
        acc[r][0] = 0.f;
        acc[r][1] = 0.f;
    }

#pragma unroll
    for (int k = 0; k < 16; k++) {
        const int i = lane + 32 * k;
        float4 v0 = __ldcs(&vp[i]);
        float4 v1 = __ldcs(&vp[512 + i]);
        __stcs(&op[i], v0);                // fused streaming copy to output
        __stcs(&op[512 + i], v1);
#pragma unroll
        for (int r = 0; r < 8; r++) {
            float4 w = sW[r * 512 + i];    // LDS.128, conflict-free
            acc[r][0] = fmaf(v0.x, w.x, acc[r][0]);
            acc[r][0] = fmaf(v0.y, w.y, acc[r][0]);
            acc[r][0] = fmaf(v0.z, w.z, acc[r][0]);
            acc[r][0] = fmaf(v0.w, w.w, acc[r][0]);
            acc[r][1] = fmaf(v1.x, w.x, acc[r][1]);
            acc[r][1] = fmaf(v1.y, w.y, acc[r][1]);
            acc[r][1] = fmaf(v1.z, w.z, acc[r][1]);
            acc[r][1] = fmaf(v1.w, w.w, acc[r][1]);
        }
    }

#pragma unroll
    for (int r = 0; r < 8; r++)
#pragma unroll
        for (int t = 0; t < 2; t++)
#pragma unroll
            for (int off = 16; off; off >>= 1)
                acc[r][t] += __shfl_xor_sync(~0u, acc[r][t], off);

    if (lane == 0) {
#pragma unroll
        for (int t = 0; t < 2; t++) {
            const int token = t0 + t;
            const int b = token >> 10, n = token & 1023;
            const int base = b * 4 * 1024 + n;
#pragma unroll
            for (int c = 0; c < 4; c++) {
                g_EA[base + c * 1024] = __expf(acc[c][t] + g_cst[c]);
                g_EB[base + c * 1024] = __expf(acc[4 + c][t]);
            }
        }
    }
}

// ---------------------------------------------------------------------------
// Kernel 3 (chunked): connections[b,c,m,n] = t/(1+t), t = EA[b,c,n]*EB[b,c,m]
// grid (64, 8) per chunk; bcOffset selects the 8 (b,c) planes (2 batches).
// Paired reciprocal: 1 MUFU.RCP per 2 sigmoids.
// ---------------------------------------------------------------------------
__global__ void k3_conn(float4* __restrict__ conn4, int bcOffset) {
    const int tid = threadIdx.x;       // 0..255 -> float4 group along n
    const int bc = bcOffset + blockIdx.y;
    const int m0 = blockIdx.x * 16;

    const float4* ea4 = reinterpret_cast<const float4*>(g_EA);
    const float4* eb4 = reinterpret_cast<const float4*>(g_EB);
    float4 ea = __ldg(&ea4[bc * 256 + tid]);

    float4 e0 = __ldg(&eb4[(bc * 1024 + m0) / 4 + 0]);
    float4 e1 = __ldg(&eb4[(bc * 1024 + m0) / 4 + 1]);
    float4 e2 = __ldg(&eb4[(bc * 1024 + m0) / 4 + 2]);
    float4 e3 = __ldg(&eb4[(bc * 1024 + m0) / 4 + 3]);
    float ebv[16] = {e0.x, e0.y, e0.z, e0.w, e1.x, e1.y, e1.z, e1.w,
                     e2.x, e2.y, e2.z, e2.w, e3.x, e3.y, e3.z, e3.w};

    size_t obase = ((size_t)bc * 1024 + m0) * 256 + tid;
#pragma unroll
    for (int j = 0; j < 16; j++) {
        const float eb = ebv[j];
        float tx = ea.x * eb, ty = ea.y * eb, tz = ea.z * eb, tw = ea.w * eb;
        float dx = 1.f + tx, dy = 1.f + ty, dz = 1.f + tz, dw = 1.f + tw;
        // One reciprocal per pair: 1/dx = R*dy, 1/dy = R*dx with R=1/(dx*dy).
        float rxy = __frcp_rn(dx * dy) * 1.0f;  // MUFU.RCP
        float rzw = __frcp_rn(dz * dw) * 1.0f;
        float4 o;
        o.x = tx * (rxy * dy);
        o.y = ty * (rxy * dx);
        o.z = tz * (rzw * dw);
        o.w = tw * (rzw * dz);
        __stcs(&conn4[obase + (size_t)j * 256], o);
    }
}

// ---------------------------------------------------------------------------
extern "C" void kernel_launch(void* const* d_in, const int* in_sizes, int n_in,
                              void* d_out, int out_size) {
    const float* vectors = (const float*)d_in[0];
    const float* W1 = (const float*)d_in[1];
    const float* b1 = (const float*)d_in[2];
    const float* W2 = (const float*)d_in[3];
    const float* b2 = (const float*)d_in[4];
    float* out = (float*)d_out;
    float4* conn4 = (float4*)(out + VEC_ELEMS);

    // Host-side resources (created once; no device memory involved).
    static cudaStream_t s2 = nullptr;
    static cudaEvent_t evFork[4], evJoin;
    if (s2 == nullptr) {
        cudaStreamCreateWithFlags(&s2, cudaStreamNonBlocking);
        for (int i = 0; i < 4; i++)
            cudaEventCreateWithFlags(&evFork[i], cudaEventDisableTiming);
        cudaEventCreateWithFlags(&evJoin, cudaEventDisableTiming);
        cudaFuncSetAttribute(k2_proj,
                             cudaFuncAttributeMaxDynamicSharedMemorySize,
                             64 * 1024);
    }

    k1_weff_part<<<dim3(16, 16), 256>>>(W1, W2);
    k1b_reduce<<<64, 256>>>(W2, b1, b2);

    // Pipeline: 4 chunks of 2 batches. k2(chunk i+1) overlaps k3(chunk i).
    for (int ci = 0; ci < 4; ci++) {
        k2_proj<<<128, 256, 64 * 1024>>>((const float4*)vectors, (float4*)out,
                                         ci * 128);
        cudaEventRecord(evFork[ci], 0);
        cudaStreamWaitEvent(s2, evFork[ci], 0);
        k3_conn<<<dim3(64, 8), 256, 0, s2>>>(conn4, ci * 8);
    }
    cudaEventRecord(evJoin, s2);
    cudaStreamWaitEvent(0, evJoin, 0);
}

// round 7
// speedup vs baseline: 1.2610x; 1.2610x over previous
#include <cuda_runtime.h>

// Problem constants
#define BB 8
#define NN 1024
#define FF 2048
#define CC 4
#define NTOK (BB * NN)            // 8192 tokens
#define VEC_ELEMS (BB * NN * FF)  // 16777216 floats
#define VEC_F4 (VEC_ELEMS / 4)    // 4194304 float4
#define BCN (BB * CC)             // 32 (b,c) pairs

// Scratch (static device globals — no allocation allowed)
__device__ float g_Wpart[32][8][2048];  // [h-chunk][row r][f], r = c + 4*half
__device__ float g_W[8 * 2048];         // Weff rows: r<4 -> Wa[c], r>=4 -> Wb[c]
__device__ float g_cst[4];              // W2 @ b1 + b2
__device__ float g_EA[BCN * NN];        // exp(p1[b,n,c] + const[c]),  [(b*4+c)*1024 + n]
__device__ float g_EB[BCN * NN];        // exp(p2[b,n,c])

// ---------------------------------------------------------------------------
// Kernel 1: partial Weff[r][f] = sum_{h in 32-chunk} W2[c][h] * W1[h][f']
// grid (16, 32): blockIdx.x -> 256-wide f' group, blockIdx.y -> 32-wide h chunk
// ---------------------------------------------------------------------------
__global__ void k1_weff_part(const float* __restrict__ W1,
                             const float* __restrict__ W2) {
    __shared__ float sW2[4 * 32];
    const int tid = threadIdx.x;
    const int h0 = blockIdx.y * 32;
    if (tid < 128) sW2[tid] = W2[(tid >> 5) * 1024 + h0 + (tid & 31)];
    __syncthreads();

    const int fp = blockIdx.x * 256 + tid;  // 0..4095 (column of W1)
    float a0 = 0.f, a1 = 0.f, a2 = 0.f, a3 = 0.f;
    const float* w1p = W1 + (size_t)h0 * 4096 + fp;
#pragma unroll
    for (int hh = 0; hh < 32; hh++) {
        float w1 = w1p[(size_t)hh * 4096];  // coalesced across warp
        a0 = fmaf(sW2[hh], w1, a0);
        a1 = fmaf(sW2[32 + hh], w1, a1);
        a2 = fmaf(sW2[64 + hh], w1, a2);
        a3 = fmaf(sW2[96 + hh], w1, a3);
    }
    const int half = fp >> 11;
    const int f = fp & 2047;
    const int rb = half * 4;
    g_Wpart[blockIdx.y][rb + 0][f] = a0;
    g_Wpart[blockIdx.y][rb + 1][f] = a1;
    g_Wpart[blockIdx.y][rb + 2][f] = a2;
    g_Wpart[blockIdx.y][rb + 3][f] = a3;
}

// ---------------------------------------------------------------------------
// Kernel 1b: reduce partials into g_W; one warp also computes g_cst
// ---------------------------------------------------------------------------
__global__ void k1b_reduce(const float* __restrict__ W2,
                           const float* __restrict__ b1,
                           const float* __restrict__ b2) {
    const int idx = blockIdx.x * 256 + threadIdx.x;  // 0..16383
    const int r = idx >> 11, f = idx & 2047;
    float s = 0.f;
#pragma unroll
    for (int p = 0; p < 32; p++) s += g_Wpart[p][r][f];
    g_W[r * 2048 + f] = s;

    if (blockIdx.x == 0 && threadIdx.x < 32) {
        const int lane = threadIdx.x;
        float c0 = 0.f, c1 = 0.f, c2 = 0.f, c3 = 0.f;
        for (int h = lane; h < 1024; h += 32) {
            float bv = b1[h];
            c0 = fmaf(W2[h], bv, c0);
            c1 = fmaf(W2[1024 + h], bv, c1);
            c2 = fmaf(W2[2048 + h], bv, c2);
            c3 = fmaf(W2[3072 + h], bv, c3);
        }
#pragma unroll
        for (int off = 16; off; off >>= 1) {
            c0 += __shfl_xor_sync(~0u, c0, off);
            c1 += __shfl_xor_sync(~0u, c1, off);
            c2 += __shfl_xor_sync(~0u, c2, off);
            c3 += __shfl_xor_sync(~0u, c3, off);
        }
        if (lane == 0) {
            g_cst[0] = c0 + b2[0];
            g_cst[1] = c1 + b2[1];
            g_cst[2] = c2 + b2[2];
            g_cst[3] = c3 + b2[3];
        }
    }
}

// ---------------------------------------------------------------------------
// Copy kernel: vectors -> out[0:VEC_ELEMS). Pure stream on a second CUDA
// stream, concurrent with k2ro/k3; reads ride k2ro's L2 lines.
// grid 1024 x 256: each block copies 64 KB contiguous.
// ---------------------------------------------------------------------------
__global__ void kcopy(const float4* __restrict__ src,
                      float4* __restrict__ dst) {
    size_t i = (size_t)blockIdx.x * 4096 + threadIdx.x;
#pragma unroll
    for (int k = 0; k < 16; k++) {
        __stcs(&dst[i], __ldcs(&src[i]));
        i += 256;
    }
}

// ---------------------------------------------------------------------------
// Kernel 2 (READ-ONLY projection): acc[r] = vectors[token,:].g_W[r,:]
// No copy stores -> clean read stream + high MLP. Weights in 64 KB smem.
// One warp per 2 tokens; 8 warps/block; grid = 512.
// ---------------------------------------------------------------------------
__global__ void __launch_bounds__(256) k2_proj(const float4* __restrict__ vec4) {
    extern __shared__ float4 sW[];  // 4096 float4 = 64 KB = all of g_W
    const float4* gW4 = reinterpret_cast<const float4*>(g_W);
    for (int s = threadIdx.x; s < 4096; s += 256) sW[s] = gW4[s];
    __syncthreads();

    const int lane = threadIdx.x & 31;
    const int wid = threadIdx.x >> 5;
    const int t0 = (blockIdx.x * 8 + wid) * 2;

    const float4* vp = vec4 + (size_t)t0 * 512;

    float acc[8][2];
#pragma unroll
    for (int r = 0; r < 8; r++) {
        acc[r][0] = 0.f;
        acc[r][1] = 0.f;
    }

#pragma unroll
    for (int k = 0; k < 16; k++) {
        const int i = lane + 32 * k;
        float4 v0 = __ldcs(&vp[i]);        // streaming read, no store dep
        float4 v1 = __ldcs(&vp[512 + i]);
#pragma unroll
        for (int r = 0; r < 8; r++) {
            float4 w = sW[r * 512 + i];    // LDS.128, conflict-free
            acc[r][0] = fmaf(v0.x, w.x, acc[r][0]);
            acc[r][0] = fmaf(v0.y, w.y, acc[r][0]);
            acc[r][0] = fmaf(v0.z, w.z, acc[r][0]);
            acc[r][0] = fmaf(v0.w, w.w, acc[r][0]);
            acc[r][1] = fmaf(v1.x, w.x, acc[r][1]);
            acc[r][1] = fmaf(v1.y, w.y, acc[r][1]);
            acc[r][1] = fmaf(v1.z, w.z, acc[r][1]);
            acc[r][1] = fmaf(v1.w, w.w, acc[r][1]);
        }
    }

#pragma unroll
    for (int r = 0; r < 8; r++)
#pragma unroll
        for (int t = 0; t < 2; t++)
#pragma unroll
            for (int off = 16; off; off >>= 1)
                acc[r][t] += __shfl_xor_sync(~0u, acc[r][t], off);

    if (lane == 0) {
#pragma unroll
        for (int t = 0; t < 2; t++) {
            const int token = t0 + t;
            const int b = token >> 10, n = token & 1023;
            const int base = b * 4 * 1024 + n;
#pragma unroll
            for (int c = 0; c < 4; c++) {
                g_EA[base + c * 1024] = __expf(acc[c][t] + g_cst[c]);
                g_EB[base + c * 1024] = __expf(acc[4 + c][t]);
            }
        }
    }
}

// ---------------------------------------------------------------------------
// Kernel 3 (monolithic, R5 version): connections[b,c,m,n] = t/(1+t)
// grid (64, 32): blockIdx.y = (b*4+c), blockIdx.x = 16-row m tile.
// ---------------------------------------------------------------------------
__global__ void k3_conn(float4* __restrict__ conn4) {
    const int tid = threadIdx.x;
    const int bc = blockIdx.y;
    const int m0 = blockIdx.x * 16;

    const float4* ea4 = reinterpret_cast<const float4*>(g_EA);
    const float4* eb4 = reinterpret_cast<const float4*>(g_EB);
    float4 ea = __ldg(&ea4[bc * 256 + tid]);

    float4 e0 = __ldg(&eb4[(bc * 1024 + m0) / 4 + 0]);
    float4 e1 = __ldg(&eb4[(bc * 1024 + m0) / 4 + 1]);
    float4 e2 = __ldg(&eb4[(bc * 1024 + m0) / 4 + 2]);
    float4 e3 = __ldg(&eb4[(bc * 1024 + m0) / 4 + 3]);
    float ebv[16] = {e0.x, e0.y, e0.z, e0.w, e1.x, e1.y, e1.z, e1.w,
                     e2.x, e2.y, e2.z, e2.w, e3.x, e3.y, e3.z, e3.w};

    size_t obase = ((size_t)bc * 1024 + m0) * 256 + tid;
#pragma unroll
    for (int j = 0; j < 16; j++) {
        const float eb = ebv[j];
        float4 o;
        float t;
        t = ea.x * eb; o.x = __fdividef(t, 1.0f + t);
        t = ea.y * eb; o.y = __fdividef(t, 1.0f + t);
        t = ea.z * eb; o.z = __fdividef(t, 1.0f + t);
        t = ea.w * eb; o.w = __fdividef(t, 1.0f + t);
        __stcs(&conn4[obase + (size_t)j * 256], o);
    }
}

// ---------------------------------------------------------------------------
extern "C" void kernel_launch(void* const* d_in, const int* in_sizes, int n_in,
                              void* d_out, int out_size) {
    const float* vectors = (const float*)d_in[0];
    const float* W1 = (const float*)d_in[1];
    const float* b1 = (const float*)d_in[2];
    const float* W2 = (const float*)d_in[3];
    const float* b2 = (const float*)d_in[4];
    float* out = (float*)d_out;
    float4* conn4 = (float4*)(out + VEC_ELEMS);

    // Host-side resources (created once, outside capture; no device memory).
    static cudaStream_t s2 = nullptr;
    static cudaEvent_t evFork, evJoin;
    if (s2 == nullptr) {
        cudaStreamCreateWithFlags(&s2, cudaStreamNonBlocking);
        cudaEventCreateWithFlags(&evFork, cudaEventDisableTiming);
        cudaEventCreateWithFlags(&evJoin, cudaEventDisableTiming);
        cudaFuncSetAttribute(k2_proj,
                             cudaFuncAttributeMaxDynamicSharedMemorySize,
                             64 * 1024);
    }

    k1_weff_part<<<dim3(16, 32), 256>>>(W1, W2);
    k1b_reduce<<<64, 256>>>(W2, b1, b2);

    // Fork: the 128 MB vectors copy runs on s2, concurrent with k2+k3.
    cudaEventRecord(evFork, 0);
    cudaStreamWaitEvent(s2, evFork, 0);
    kcopy<<<1024, 256, 0, s2>>>((const float4*)vectors, (float4*)out);

    k2_proj<<<512, 256, 64 * 1024>>>((const float4*)vectors);
    k3_conn<<<dim3(64, 32), 256>>>(conn4);

    // Join: main stream completes only after the copy finishes.
    cudaEventRecord(evJoin, s2);
    cudaStreamWaitEvent(0, evJoin, 0);
}

// round 8
// speedup vs baseline: 1.7088x; 1.3552x over previous
#include <cuda_runtime.h>

// Problem constants
#define BB 8
#define NN 1024
#define FF 2048
#define CC 4
#define NTOK (BB * NN)            // 8192 tokens
#define VEC_ELEMS (BB * NN * FF)  // 16777216 floats
#define BCN (BB * CC)             // 32 (b,c) pairs

// Scratch (static device globals — no allocation allowed)
__device__ float g_Wpart[32][8][2048];  // [h-chunk][row r][f], r = c + 4*half
__device__ float g_W[8 * 2048];         // Weff rows: r<4 -> Wa[c], r>=4 -> Wb[c]
__device__ float g_cst[4];              // W2 @ b1 + b2
__device__ float g_EA[BCN * NN];        // exp(p1[b,n,c] + const[c])
__device__ float g_EB[BCN * NN];        // exp(p2[b,n,c])

// Packed fp32x2 FMA: acc.(lo,hi) += v.(lo,hi) * w.(lo,hi)   (Blackwell f32x2)
__device__ __forceinline__ void fma2(unsigned long long& a,
                                     unsigned long long v,
                                     unsigned long long w) {
    asm("fma.rn.f32x2 %0, %1, %2, %0;" : "+l"(a) : "l"(v), "l"(w));
}

// ---------------------------------------------------------------------------
// Kernel 1: partial Weff[r][f] = sum_{h in 32-chunk} W2[c][h] * W1[h][f']
// ---------------------------------------------------------------------------
__global__ void k1_weff_part(const float* __restrict__ W1,
                             const float* __restrict__ W2) {
    __shared__ float sW2[4 * 32];
    const int tid = threadIdx.x;
    const int h0 = blockIdx.y * 32;
    if (tid < 128) sW2[tid] = W2[(tid >> 5) * 1024 + h0 + (tid & 31)];
    __syncthreads();

    const int fp = blockIdx.x * 256 + tid;  // 0..4095 (column of W1)
    float a0 = 0.f, a1 = 0.f, a2 = 0.f, a3 = 0.f;
    const float* w1p = W1 + (size_t)h0 * 4096 + fp;
#pragma unroll
    for (int hh = 0; hh < 32; hh++) {
        float w1 = w1p[(size_t)hh * 4096];
        a0 = fmaf(sW2[hh], w1, a0);
        a1 = fmaf(sW2[32 + hh], w1, a1);
        a2 = fmaf(sW2[64 + hh], w1, a2);
        a3 = fmaf(sW2[96 + hh], w1, a3);
    }
    const int half = fp >> 11;
    const int f = fp & 2047;
    const int rb = half * 4;
    g_Wpart[blockIdx.y][rb + 0][f] = a0;
    g_Wpart[blockIdx.y][rb + 1][f] = a1;
    g_Wpart[blockIdx.y][rb + 2][f] = a2;
    g_Wpart[blockIdx.y][rb + 3][f] = a3;
}

// ---------------------------------------------------------------------------
// Kernel 1b: reduce partials into g_W; one warp also computes g_cst
// ---------------------------------------------------------------------------
__global__ void k1b_reduce(const float* __restrict__ W2,
                           const float* __restrict__ b1,
                           const float* __restrict__ b2) {
    const int idx = blockIdx.x * 256 + threadIdx.x;  // 0..16383
    const int r = idx >> 11, f = idx & 2047;
    float s = 0.f;
#pragma unroll
    for (int p = 0; p < 32; p++) s += g_Wpart[p][r][f];
    g_W[r * 2048 + f] = s;

    if (blockIdx.x == 0 && threadIdx.x < 32) {
        const int lane = threadIdx.x;
        float c0 = 0.f, c1 = 0.f, c2 = 0.f, c3 = 0.f;
        for (int h = lane; h < 1024; h += 32) {
            float bv = b1[h];
            c0 = fmaf(W2[h], bv, c0);
            c1 = fmaf(W2[1024 + h], bv, c1);
            c2 = fmaf(W2[2048 + h], bv, c2);
            c3 = fmaf(W2[3072 + h], bv, c3);
        }
#pragma unroll
        for (int off = 16; off; off >>= 1) {
            c0 += __shfl_xor_sync(~0u, c0, off);
            c1 += __shfl_xor_sync(~0u, c1, off);
            c2 += __shfl_xor_sync(~0u, c2, off);
            c3 += __shfl_xor_sync(~0u, c3, off);
        }
        if (lane == 0) {
            g_cst[0] = c0 + b2[0];
            g_cst[1] = c1 + b2[1];
            g_cst[2] = c2 + b2[2];
            g_cst[3] = c3 + b2[3];
        }
    }
}

// ---------------------------------------------------------------------------
// Kernel 2: projections + fused vectors copy.
// R8: explicit MLP. k-loop in 4 chunks of 4 steps; next chunk's 8 LDG.128
// issued before current chunk's FMAs (double buffer). FMAs use packed
// fp32x2 (fma.rn.f32x2) on natural 64-bit pairs from the 128-bit loads.
// 2 tokens/warp, weights staged in 64 KB smem, __launch_bounds__(256,2).
// ---------------------------------------------------------------------------
__global__ void __launch_bounds__(256, 2)
k2_proj(const ulonglong2* __restrict__ vecu, ulonglong2* __restrict__ outu) {
    extern __shared__ ulonglong2 sW[];  // 4096 * 16 B = 64 KB = all of g_W

    const int lane = threadIdx.x & 31;
    const int wid = threadIdx.x >> 5;
    const int t0 = (blockIdx.x * 8 + wid) * 2;

    const ulonglong2* vp = vecu + (size_t)t0 * 512;
    ulonglong2* op = outu + (size_t)t0 * 512;

    // Prologue: issue chunk-0 v loads BEFORE weight staging (overlap).
    ulonglong2 va[2][4], vb[2][4];
#pragma unroll
    for (int u = 0; u < 4; u++) {
        va[0][u] = __ldcs(&vp[lane + 32 * u]);
        vb[0][u] = __ldcs(&vp[512 + lane + 32 * u]);
    }

    // Stage weights into smem.
    const ulonglong2* gWu = reinterpret_cast<const ulonglong2*>(g_W);
    for (int s = threadIdx.x; s < 4096; s += 256) sW[s] = gWu[s];
    __syncthreads();

    unsigned long long acc[8][2];  // f32x2 partial sums (even/odd lanes)
#pragma unroll
    for (int r = 0; r < 8; r++) {
        acc[r][0] = 0ull;
        acc[r][1] = 0ull;
    }

#pragma unroll
    for (int ch = 0; ch < 4; ch++) {
        const int cur = ch & 1, nxt = cur ^ 1;
        const int base = lane + 128 * ch;
        // Prefetch next chunk (8 independent LDG.128 in flight during FMAs).
        if (ch < 3) {
#pragma unroll
            for (int u = 0; u < 4; u++) {
                va[nxt][u] = __ldcs(&vp[base + 128 + 32 * u]);
                vb[nxt][u] = __ldcs(&vp[512 + base + 128 + 32 * u]);
            }
        }
        // Fused streaming copy (stores drain during FMA phase).
#pragma unroll
        for (int u = 0; u < 4; u++) {
            __stcs(&op[base + 32 * u], va[cur][u]);
            __stcs(&op[512 + base + 32 * u], vb[cur][u]);
        }
        // Packed FMAs: 32 fma.f32x2 per k-step instead of 64 FFMA.
#pragma unroll
        for (int u = 0; u < 4; u++) {
            const int i = base + 32 * u;
            const ulonglong2 v0 = va[cur][u];
            const ulonglong2 v1 = vb[cur][u];
#pragma unroll
            for (int r = 0; r < 8; r++) {
                const ulonglong2 w = sW[r * 512 + i];
                fma2(acc[r][0], v0.x, w.x);
                fma2(acc[r][0], v0.y, w.y);
                fma2(acc[r][1], v1.x, w.x);
                fma2(acc[r][1], v1.y, w.y);
            }
        }
    }

    // Horizontal: f32x2 -> scalar, then warp reduce.
    float facc[8][2];
#pragma unroll
    for (int r = 0; r < 8; r++)
#pragma unroll
        for (int t = 0; t < 2; t++) {
            float2 p = *reinterpret_cast<float2*>(&acc[r][t]);
            float s = p.x + p.y;
#pragma unroll
            for (int off = 16; off; off >>= 1)
                s += __shfl_xor_sync(~0u, s, off);
            facc[r][t] = s;
        }

    if (lane == 0) {
#pragma unroll
        for (int t = 0; t < 2; t++) {
            const int token = t0 + t;
            const int b = token >> 10, n = token & 1023;
            const int base = b * 4 * 1024 + n;
#pragma unroll
            for (int c = 0; c < 4; c++) {
                g_EA[base + c * 1024] = __expf(facc[c][t] + g_cst[c]);
                g_EB[base + c * 1024] = __expf(facc[4 + c][t]);
            }
        }
    }
}

// ---------------------------------------------------------------------------
// Kernel 3: connections[b,c,m,n] = t/(1+t),  t = EA[b,c,n] * EB[b,c,m]
// ---------------------------------------------------------------------------
__global__ void k3_conn(float4* __restrict__ conn4) {
    const int tid = threadIdx.x;
    const int bc = blockIdx.y;
    const int m0 = blockIdx.x * 16;

    const float4* ea4 = reinterpret_cast<const float4*>(g_EA);
    const float4* eb4 = reinterpret_cast<const float4*>(g_EB);
    float4 ea = __ldg(&ea4[bc * 256 + tid]);

    float4 e0 = __ldg(&eb4[(bc * 1024 + m0) / 4 + 0]);
    float4 e1 = __ldg(&eb4[(bc * 1024 + m0) / 4 + 1]);
    float4 e2 = __ldg(&eb4[(bc * 1024 + m0) / 4 + 2]);
    float4 e3 = __ldg(&eb4[(bc * 1024 + m0) / 4 + 3]);
    float ebv[16] = {e0.x, e0.y, e0.z, e0.w, e1.x, e1.y, e1.z, e1.w,
                     e2.x, e2.y, e2.z, e2.w, e3.x, e3.y, e3.z, e3.w};

    size_t obase = ((size_t)bc * 1024 + m0) * 256 + tid;
#pragma unroll
    for (int j = 0; j < 16; j++) {
        const float eb = ebv[j];
        float4 o;
        float t;
        t = ea.x * eb; o.x = __fdividef(t, 1.0f + t);
        t = ea.y * eb; o.y = __fdividef(t, 1.0f + t);
        t = ea.z * eb; o.z = __fdividef(t, 1.0f + t);
        t = ea.w * eb; o.w = __fdividef(t, 1.0f + t);
        __stcs(&conn4[obase + (size_t)j * 256], o);
    }
}

// ---------------------------------------------------------------------------
extern "C" void kernel_launch(void* const* d_in, const int* in_sizes, int n_in,
                              void* d_out, int out_size) {
    const float* vectors = (const float*)d_in[0];
    const float* W1 = (const float*)d_in[1];
    const float* b1 = (const float*)d_in[2];
    const float* W2 = (const float*)d_in[3];
    const float* b2 = (const float*)d_in[4];
    float* out = (float*)d_out;

    cudaFuncSetAttribute(k2_proj, cudaFuncAttributeMaxDynamicSharedMemorySize,
                         64 * 1024);

    k1_weff_part<<<dim3(16, 32), 256>>>(W1, W2);
    k1b_reduce<<<64, 256>>>(W2, b1, b2);
    k2_proj<<<512, 256, 64 * 1024>>>((const ulonglong2*)vectors,
                                     (ulonglong2*)out);
    k3_conn<<<dim3(64, 32), 256>>>((float4*)(out + VEC_ELEMS));
}